// round 1
// baseline (speedup 1.0000x reference)
#include <cuda_runtime.h>
#include <math.h>

#define V    256
#define HA   2048
#define HHP  4096
#define HS   2048   // H_HP / 2
#define DEPTH 12

// ---------------- persistent state (device globals; no allocation) ----------------
__device__ float g_h_a[2][HA];
__device__ float g_c_a[2][HA];
__device__ float g_c_hp[2][HHP];
__device__ float g_h_hp[HHP];
__device__ float g_a[V];
__device__ float g_a_hp[V];
__device__ float g_h_sum[HS];
__device__ float g_logits[V];

// ---------------- helpers ----------------
__device__ __forceinline__ float sigm(float x) { return 1.f / (1.f + expf(-x)); }

// strided float4 dot-product partial (per thread)
__device__ __forceinline__ float dot4(const float* __restrict__ W,
                                      const float* __restrict__ x,
                                      int C4, int tid, int nt) {
    float s = 0.f;
    const float4* __restrict__ W4 = (const float4*)W;
    const float4* __restrict__ x4 = (const float4*)x;
    for (int t = tid; t < C4; t += nt) {
        float4 w = W4[t];
        float4 v = x4[t];
        s = fmaf(w.x, v.x, s);
        s = fmaf(w.y, v.y, s);
        s = fmaf(w.z, v.z, s);
        s = fmaf(w.w, v.w, s);
    }
    return s;
}

// block sum-reduction; result valid on thread 0. Safe for repeated use.
__device__ __forceinline__ float block_reduce(float v, float* sh) {
    int lane = threadIdx.x & 31, w = threadIdx.x >> 5, nw = blockDim.x >> 5;
    #pragma unroll
    for (int o = 16; o; o >>= 1) v += __shfl_down_sync(0xffffffffu, v, o);
    if (lane == 0) sh[w] = v;
    __syncthreads();
    if (w == 0) {
        v = (lane < nw) ? sh[lane] : 0.f;
        #pragma unroll
        for (int o = 16; o; o >>= 1) v += __shfl_down_sync(0xffffffffu, v, o);
    }
    __syncthreads();  // allow sh reuse
    return v;
}

// ---------------- kernels ----------------
__global__ void init_kernel(const float* __restrict__ xa, const float* __restrict__ xhp) {
    int i = blockIdx.x * blockDim.x + threadIdx.x;
    if (i < HA)  { g_h_a[0][i] = xa[i];  g_c_a[0][i] = 0.f; }
    if (i < HHP) { g_h_hp[i]   = xhp[i]; g_c_hp[0][i] = 0.f; }
    if (i < V)   { g_a[i] = 1.f / V; g_a_hp[i] = 1.f / V; }
}

// Fused LSTM step: one block per hidden unit j. Computes all 4 gate rows
// (gate order i,f,g,o along 4H) and applies the cell update.
// x = concat(x0[Cx0], x1[Cx1]); hidden vector hv[Ch]; cell-in = concat(c0[Hc0], c1[...]).
__global__ void lstm_kernel(const float* __restrict__ Wih, const float* __restrict__ Whh,
                            const float* __restrict__ bih, const float* __restrict__ bhh,
                            const float* __restrict__ x0, int Cx0,
                            const float* __restrict__ x1, int Cx1,
                            const float* __restrict__ hv, int Ch,
                            const float* __restrict__ c0, const float* __restrict__ c1, int Hc0,
                            float* __restrict__ h_out, float* __restrict__ c_out) {
    const int j = blockIdx.x;
    const int H = gridDim.x;
    const int tid = threadIdx.x, nt = blockDim.x;
    const int Cx = Cx0 + Cx1;
    __shared__ float sh[32];

    float gv[4];
    #pragma unroll
    for (int g = 0; g < 4; ++g) {
        const size_t row = (size_t)(g * H + j);
        const float* rih = Wih + row * (size_t)Cx;
        float p = dot4(rih, x0, Cx0 >> 2, tid, nt);
        if (Cx1) p += dot4(rih + Cx0, x1, Cx1 >> 2, tid, nt);
        p += dot4(Whh + row * (size_t)Ch, hv, Ch >> 2, tid, nt);
        float s = block_reduce(p, sh);
        gv[g] = s;  // only thread 0's value is the full sum
    }
    if (tid == 0) {
        float gi = sigm(gv[0] + bih[0 * H + j] + bhh[0 * H + j]);
        float gf = sigm(gv[1] + bih[1 * H + j] + bhh[1 * H + j]);
        float gg = tanhf(gv[2] + bih[2 * H + j] + bhh[2 * H + j]);
        float go = sigm(gv[3] + bih[3 * H + j] + bhh[3 * H + j]);
        float cold = (j < Hc0) ? c0[j] : c1[j - Hc0];
        float cn = gf * cold + gi * gg;
        c_out[j] = cn;
        h_out[j] = go * tanhf(cn);
    }
}

// y[r] = act(W[r,:] . x + b[r]); one block per output row
__global__ void linear_kernel(const float* __restrict__ W, const float* __restrict__ b,
                              const float* __restrict__ x, int C,
                              float* __restrict__ y, int relu) {
    const int r = blockIdx.x;
    __shared__ float sh[32];
    float p = dot4(W + (size_t)r * C, x, C >> 2, threadIdx.x, blockDim.x);
    float s = block_reduce(p, sh);
    if (threadIdx.x == 0) {
        s += b[r];
        if (relu) s = fmaxf(s, 0.f);
        y[r] = s;
    }
}

// single-block softmax over V=256 logits; writes recurrent vector and output row
__global__ void softmax_kernel(const float* __restrict__ logits,
                               float* __restrict__ avec, float* __restrict__ outrow) {
    __shared__ float sh[8];
    const int tid = threadIdx.x;
    float v = logits[tid];
    float m = v;
    #pragma unroll
    for (int o = 16; o; o >>= 1) m = fmaxf(m, __shfl_xor_sync(0xffffffffu, m, o));
    if ((tid & 31) == 0) sh[tid >> 5] = m;
    __syncthreads();
    float bm = sh[0];
    #pragma unroll
    for (int w = 1; w < 8; ++w) bm = fmaxf(bm, sh[w]);
    float e = expf(v - bm);
    float s = e;
    #pragma unroll
    for (int o = 16; o; o >>= 1) s += __shfl_xor_sync(0xffffffffu, s, o);
    __syncthreads();
    if ((tid & 31) == 0) sh[tid >> 5] = s;
    __syncthreads();
    float bs = 0.f;
    #pragma unroll
    for (int w = 0; w < 8; ++w) bs += sh[w];
    float r = e / bs;
    avec[tid] = r;
    outrow[tid] = r;
}

// ---------------- launch ----------------
extern "C" void kernel_launch(void* const* d_in, const int* in_sizes, int n_in,
                              void* d_out, int out_size) {
    const float* x_a     = (const float*)d_in[0];
    const float* x_hp    = (const float*)d_in[1];
    const float* W_ih_a  = (const float*)d_in[2];
    const float* W_hh_a  = (const float*)d_in[3];
    const float* b_ih_a  = (const float*)d_in[4];
    const float* b_hh_a  = (const float*)d_in[5];
    const float* W_out_a = (const float*)d_in[6];
    const float* b_out_a = (const float*)d_in[7];
    const float* W_sum   = (const float*)d_in[8];
    const float* b_sum   = (const float*)d_in[9];
    const float* W_ih_hp = (const float*)d_in[10];
    const float* W_hh_hp = (const float*)d_in[11];
    const float* b_ih_hp = (const float*)d_in[12];
    const float* b_hh_hp = (const float*)d_in[13];
    const float* W_out_hp= (const float*)d_in[14];
    const float* b_out_hp= (const float*)d_in[15];
    float* out = (float*)d_out;

    float *h_a, *c_a, *c_hp, *h_hp, *a, *a_hp, *h_sum, *logits;
    cudaGetSymbolAddress((void**)&h_a,    g_h_a);
    cudaGetSymbolAddress((void**)&c_a,    g_c_a);
    cudaGetSymbolAddress((void**)&c_hp,   g_c_hp);
    cudaGetSymbolAddress((void**)&h_hp,   g_h_hp);
    cudaGetSymbolAddress((void**)&a,      g_a);
    cudaGetSymbolAddress((void**)&a_hp,   g_a_hp);
    cudaGetSymbolAddress((void**)&h_sum,  g_h_sum);
    cudaGetSymbolAddress((void**)&logits, g_logits);

    init_kernel<<<(HHP + 255) / 256, 256>>>(x_a, x_hp);

    for (int s = 0; s < DEPTH; ++s) {
        const int pp = s & 1;
        float* hA_in  = h_a  + pp * HA;
        float* hA_out = h_a  + (pp ^ 1) * HA;
        float* cA_in  = c_a  + pp * HA;
        float* cA_out = c_a  + (pp ^ 1) * HA;
        float* cHP_in  = c_hp + pp * HHP;
        float* cHP_out = c_hp + (pp ^ 1) * HHP;

        // arch LSTM: x = a(V), h = h_a, c = c_a
        lstm_kernel<<<HA, 256>>>(W_ih_a, W_hh_a, b_ih_a, b_hh_a,
                                 a, V, nullptr, 0,
                                 hA_in, HA,
                                 cA_in, cA_in, HA,
                                 hA_out, cA_out);
        // a = softmax(h_a @ W_out_a^T + b)
        linear_kernel<<<V, 256>>>(W_out_a, b_out_a, hA_out, HA, logits, 0);
        softmax_kernel<<<1, V>>>(logits, a, out + s * V);

        // h_sum = relu(h_hp @ W_sum^T + b_sum)
        linear_kernel<<<HS, 256>>>(W_sum, b_sum, h_hp, HHP, h_sum, 1);

        // hp LSTM with swapped states: x = concat(a, a_hp), hidden = c_hp,
        // cell-in = concat(h_a_new, h_sum); outputs (h_hp, c_hp)
        lstm_kernel<<<HHP, 256>>>(W_ih_hp, W_hh_hp, b_ih_hp, b_hh_hp,
                                  a, V, a_hp, V,
                                  cHP_in, HHP,
                                  hA_out, h_sum, HA,
                                  h_hp, cHP_out);

        // a_hp = softmax(h_hp @ W_out_hp^T + b)
        linear_kernel<<<V, 256>>>(W_out_hp, b_out_hp, h_hp, HHP, logits, 0);
        softmax_kernel<<<1, V>>>(logits, a_hp, out + DEPTH * V + s * V);
    }
}

// round 2
// speedup vs baseline: 1.2103x; 1.2103x over previous
#include <cuda_runtime.h>
#include <cuda_fp16.h>
#include <math.h>

#define V    256
#define HA   2048
#define HHP  4096
#define HS   2048
#define DEPTH 12

// ---------------- fp16 weight storage (device globals; no allocation) ----------------
__device__ __half g_W_ih_a[4 * HA * V];
__device__ __half g_W_hh_a[4 * HA * HA];
__device__ __half g_W_out_a[V * HA];
__device__ __half g_W_sum[HS * HHP];
__device__ __half g_W_ih_hp[4 * HHP * (2 * V)];
__device__ __half g_W_hh_hp[4 * HHP * HHP];
__device__ __half g_W_out_hp[V * HHP];

// ---------------- persistent state ----------------
__device__ float g_h_a[2][HA];
__device__ float g_c_a[2][HA];
__device__ float g_c_hp[2][HHP];
__device__ float g_h_hp[HHP];
__device__ float g_a[V];
__device__ float g_a_hp[V];
__device__ float g_h_sum[HS];
__device__ float g_logits[V];
__device__ unsigned g_cnt = 0;

__device__ __forceinline__ float sigm(float x) { return 1.f / (1.f + expf(-x)); }

// ---------------- fp32 -> fp16 weight conversion (runs once per call) ----------------
__global__ void convert_kernel(const float* __restrict__ s0, const float* __restrict__ s1,
                               const float* __restrict__ s2, const float* __restrict__ s3,
                               const float* __restrict__ s4, const float* __restrict__ s5,
                               const float* __restrict__ s6) {
    const size_t n0 = 4ull * HA * V, n1 = 4ull * HA * HA, n2 = (size_t)V * HA,
                 n3 = (size_t)HS * HHP, n4 = 4ull * HHP * 2 * V, n5 = 4ull * HHP * HHP,
                 n6 = (size_t)V * HHP;
    const size_t tot4 = (n0 + n1 + n2 + n3 + n4 + n5 + n6) / 4;
    for (size_t i4 = blockIdx.x * (size_t)blockDim.x + threadIdx.x; i4 < tot4;
         i4 += (size_t)gridDim.x * blockDim.x) {
        size_t i = i4 * 4;
        const float* s; __half* d;
        if (i < n0)              { s = s0; d = g_W_ih_a; }
        else if ((i -= n0) < n1) { s = s1; d = g_W_hh_a; }
        else if ((i -= n1) < n2) { s = s2; d = g_W_out_a; }
        else if ((i -= n2) < n3) { s = s3; d = g_W_sum; }
        else if ((i -= n3) < n4) { s = s4; d = g_W_ih_hp; }
        else if ((i -= n4) < n5) { s = s5; d = g_W_hh_hp; }
        else                     { i -= n5; s = s6; d = g_W_out_hp; }
        float4 v = *(const float4*)(s + i);
        __half2 lo = __floats2half2_rn(v.x, v.y);
        __half2 hi = __floats2half2_rn(v.z, v.w);
        uint2 u = make_uint2(*(unsigned*)&lo, *(unsigned*)&hi);
        *(uint2*)(d + i) = u;
    }
}

__global__ void init_kernel(const float* __restrict__ xa, const float* __restrict__ xhp) {
    int i = blockIdx.x * blockDim.x + threadIdx.x;
    if (i < HA)  { g_h_a[0][i] = xa[i];  g_c_a[0][i] = 0.f; }
    if (i < HHP) { g_h_hp[i]   = xhp[i]; g_c_hp[0][i] = 0.f; }
    if (i < V)   { g_a[i] = 1.f / V; g_a_hp[i] = 1.f / V; }
}

// ---------------- shared reduction helper (blockDim == 256, 8 warps) ----------------
// Reduces N per-thread partials (N*8 must be 32 or 64); results in red2[0..N-1].
template <int N>
__device__ __forceinline__ void multi_reduce(const float* acc, float* red, float* red2) {
    const int lane = threadIdx.x & 31, w = threadIdx.x >> 5;
    #pragma unroll
    for (int k = 0; k < N; ++k) {
        float v = acc[k];
        #pragma unroll
        for (int o = 16; o; o >>= 1) v += __shfl_down_sync(0xffffffffu, v, o);
        if (lane == 0) red[k * 8 + w] = v;
    }
    __syncthreads();
    if (threadIdx.x < N * 8) {
        float v = red[threadIdx.x];
        #pragma unroll
        for (int o = 4; o; o >>= 1) v += __shfl_down_sync(0xffffffffu, v, o, 8);
        if ((threadIdx.x & 7) == 0) red2[threadIdx.x >> 3] = v;
    }
    __syncthreads();
}

// dot over C elems: fp16 weights (int2 = 4 halves) vs fp32 x in smem (float4), stride nt
__device__ __forceinline__ float dot_h(const __half* __restrict__ W,
                                       const float* __restrict__ sx,
                                       int C4, int tid, int nt) {
    float s = 0.f;
    const int2* __restrict__ W2 = (const int2*)W;
    const float4* __restrict__ x4 = (const float4*)sx;
    for (int t = tid; t < C4; t += nt) {
        int2 w2 = W2[t];
        float2 wa = __half22float2(*(__half2*)&w2.x);
        float2 wb = __half22float2(*(__half2*)&w2.y);
        float4 xv = x4[t];
        s = fmaf(wa.x, xv.x, s);
        s = fmaf(wa.y, xv.y, s);
        s = fmaf(wb.x, xv.z, s);
        s = fmaf(wb.y, xv.w, s);
    }
    return s;
}

// ---------------- LSTM block: R hidden units (4R gate rows), x staged in smem -------
template <int R>
__device__ void lstm_block(int j0, int H,
                           const __half* __restrict__ Wih, const __half* __restrict__ Whh,
                           const float* __restrict__ bih, const float* __restrict__ bhh,
                           const float* __restrict__ x0, int Cx0,
                           const float* __restrict__ x1, int Cx1,
                           const float* __restrict__ hv, int Ch,
                           const float* __restrict__ c0, const float* __restrict__ c1, int Hc0,
                           float* __restrict__ h_out, float* __restrict__ c_out,
                           float* sx, float* red, float* red2) {
    const int tid = threadIdx.x, nt = blockDim.x;
    const int Cx = Cx0 + Cx1;
    for (int t = tid; t < Cx0 / 4; t += nt) ((float4*)sx)[t] = ((const float4*)x0)[t];
    if (Cx1)
        for (int t = tid; t < Cx1 / 4; t += nt)
            ((float4*)(sx + Cx0))[t] = ((const float4*)x1)[t];
    for (int t = tid; t < Ch / 4; t += nt)
        ((float4*)(sx + Cx))[t] = ((const float4*)hv)[t];
    __syncthreads();

    float acc[4 * R];
    #pragma unroll
    for (int r = 0; r < R; ++r) {
        const int j = j0 + r;
        #pragma unroll
        for (int g = 0; g < 4; ++g) {
            const size_t row = (size_t)(g * H + j);
            float s = dot_h(Wih + row * (size_t)Cx, sx, Cx / 4, tid, nt);
            s += dot_h(Whh + row * (size_t)Ch, sx + Cx, Ch / 4, tid, nt);
            acc[r * 4 + g] = s;
        }
    }
    multi_reduce<4 * R>(acc, red, red2);
    if (tid < R) {
        const int j = j0 + tid;
        const float* g4 = red2 + tid * 4;
        float gi = sigm(g4[0] + bih[0 * H + j] + bhh[0 * H + j]);
        float gf = sigm(g4[1] + bih[1 * H + j] + bhh[1 * H + j]);
        float gg = tanhf(g4[2] + bih[2 * H + j] + bhh[2 * H + j]);
        float go = sigm(g4[3] + bih[3 * H + j] + bhh[3 * H + j]);
        float cold = (j < Hc0) ? c0[j] : c1[j - Hc0];
        float cn = gf * cold + gi * gg;
        c_out[j] = cn;
        h_out[j] = go * tanhf(cn);
    }
}

// ---------------- Linear block: R rows, x staged in smem ----------------
template <int R>
__device__ void linear_block(int r0, const __half* __restrict__ W, const float* __restrict__ b,
                             int C, const float* __restrict__ x, float* __restrict__ y,
                             int relu, float* sx, float* red, float* red2) {
    const int tid = threadIdx.x, nt = blockDim.x;
    for (int t = tid; t < C / 4; t += nt) ((float4*)sx)[t] = ((const float4*)x)[t];
    __syncthreads();
    float acc[R];
    #pragma unroll
    for (int r = 0; r < R; ++r)
        acc[r] = dot_h(W + (size_t)(r0 + r) * C, sx, C / 4, tid, nt);
    multi_reduce<R>(acc, red, red2);
    if (tid < R) {
        float s = red2[tid] + b[r0 + tid];
        if (relu) s = fmaxf(s, 0.f);
        y[r0 + tid] = s;
    }
}

// ---------------- K1: arch LSTM (1024 blocks, 2 units each) + summarizer (512 blocks, 4 rows) ----
__global__ __launch_bounds__(256) void k1_kernel(
    const __half* __restrict__ Wih_a, const __half* __restrict__ Whh_a,
    const float* __restrict__ bih_a, const float* __restrict__ bhh_a,
    const float* __restrict__ a, const float* __restrict__ hA_in,
    const float* __restrict__ cA_in, float* __restrict__ hA_out, float* __restrict__ cA_out,
    const __half* __restrict__ Wsum, const float* __restrict__ bsum,
    const float* __restrict__ hhp, float* __restrict__ hsum) {
    __shared__ float sx[HHP];          // max(256+2048, 4096)
    __shared__ float red[64], red2[8];
    if (blockIdx.x < HA / 2) {
        lstm_block<2>(2 * blockIdx.x, HA, Wih_a, Whh_a, bih_a, bhh_a,
                      a, V, nullptr, 0, hA_in, HA, cA_in, cA_in, HA,
                      hA_out, cA_out, sx, red, red2);
    } else {
        linear_block<4>((blockIdx.x - HA / 2) * 4, Wsum, bsum, HHP, hhp, hsum, 1,
                        sx, red, red2);
    }
}

// ---------------- K3: hp LSTM (2048 blocks, 2 units each) ----------------
__global__ __launch_bounds__(256) void k3_kernel(
    const __half* __restrict__ Wih, const __half* __restrict__ Whh,
    const float* __restrict__ bih, const float* __restrict__ bhh,
    const float* __restrict__ a, const float* __restrict__ ahp,
    const float* __restrict__ chp_in, const float* __restrict__ hA_new,
    const float* __restrict__ hsum, float* __restrict__ hhp_out, float* __restrict__ chp_out) {
    __shared__ float sx[2 * V + HHP];  // 4608
    __shared__ float red[64], red2[8];
    lstm_block<2>(2 * blockIdx.x, HHP, Wih, Whh, bih, bhh,
                  a, V, ahp, V, chp_in, HHP, hA_new, hsum, HA,
                  hhp_out, chp_out, sx, red, red2);
}

// ---------------- out-linear + softmax fused (16 blocks; last-arriving block does softmax) ----
__global__ __launch_bounds__(256) void outsoft_kernel(
    const __half* __restrict__ W, const float* __restrict__ b,
    const float* __restrict__ x, int C,
    float* __restrict__ avec, float* __restrict__ outrow) {
    const int tid = threadIdx.x, lane = tid & 31, w = tid >> 5;
    const int C4 = C / 4;
    // each warp computes 2 rows (warp-level dot, x from global/L2)
    #pragma unroll
    for (int rr = 0; rr < 2; ++rr) {
        const int row = blockIdx.x * 16 + w * 2 + rr;
        const __half* wr = W + (size_t)row * C;
        const int2* W2 = (const int2*)wr;
        const float4* x4 = (const float4*)x;
        float s = 0.f;
        for (int t = lane; t < C4; t += 32) {
            int2 w2 = W2[t];
            float2 wa = __half22float2(*(__half2*)&w2.x);
            float2 wb = __half22float2(*(__half2*)&w2.y);
            float4 xv = __ldg(x4 + t);
            s = fmaf(wa.x, xv.x, s);
            s = fmaf(wa.y, xv.y, s);
            s = fmaf(wb.x, xv.z, s);
            s = fmaf(wb.y, xv.w, s);
        }
        #pragma unroll
        for (int o = 16; o; o >>= 1) s += __shfl_down_sync(0xffffffffu, s, o);
        if (lane == 0) g_logits[row] = s + b[row];
    }
    // grid arrival: the last block to finish performs the softmax (no spin)
    __shared__ int is_last;
    __syncthreads();
    if (tid == 0) {
        __threadfence();
        unsigned v = atomicAdd(&g_cnt, 1u);
        is_last = (v == gridDim.x - 1);
    }
    __syncthreads();
    if (!is_last) return;

    __shared__ float sm[8];
    float v = __ldcg(&g_logits[tid]);
    float m = v;
    #pragma unroll
    for (int o = 16; o; o >>= 1) m = fmaxf(m, __shfl_xor_sync(0xffffffffu, m, o));
    if (lane == 0) sm[w] = m;
    __syncthreads();
    float bm = sm[0];
    #pragma unroll
    for (int k = 1; k < 8; ++k) bm = fmaxf(bm, sm[k]);
    float e = expf(v - bm);
    float s = e;
    #pragma unroll
    for (int o = 16; o; o >>= 1) s += __shfl_xor_sync(0xffffffffu, s, o);
    __syncthreads();
    if (lane == 0) sm[w] = s;
    __syncthreads();
    float bs = 0.f;
    #pragma unroll
    for (int k = 0; k < 8; ++k) bs += sm[k];
    float r = e / bs;
    avec[tid] = r;
    outrow[tid] = r;
    if (tid == 0) g_cnt = 0;
}

// ---------------- launch ----------------
extern "C" void kernel_launch(void* const* d_in, const int* in_sizes, int n_in,
                              void* d_out, int out_size) {
    const float* x_a      = (const float*)d_in[0];
    const float* x_hp     = (const float*)d_in[1];
    const float* W_ih_a   = (const float*)d_in[2];
    const float* W_hh_a   = (const float*)d_in[3];
    const float* b_ih_a   = (const float*)d_in[4];
    const float* b_hh_a   = (const float*)d_in[5];
    const float* W_out_a  = (const float*)d_in[6];
    const float* b_out_a  = (const float*)d_in[7];
    const float* W_sum    = (const float*)d_in[8];
    const float* b_sum    = (const float*)d_in[9];
    const float* W_ih_hp  = (const float*)d_in[10];
    const float* W_hh_hp  = (const float*)d_in[11];
    const float* b_ih_hp  = (const float*)d_in[12];
    const float* b_hh_hp  = (const float*)d_in[13];
    const float* W_out_hp = (const float*)d_in[14];
    const float* b_out_hp = (const float*)d_in[15];
    float* out = (float*)d_out;

    float *h_a, *c_a, *c_hp, *h_hp, *a, *a_hp, *h_sum;
    __half *wiha, *whha, *wouta, *wsum, *wihhp, *whhhp, *wouthp;
    cudaGetSymbolAddress((void**)&h_a,   g_h_a);
    cudaGetSymbolAddress((void**)&c_a,   g_c_a);
    cudaGetSymbolAddress((void**)&c_hp,  g_c_hp);
    cudaGetSymbolAddress((void**)&h_hp,  g_h_hp);
    cudaGetSymbolAddress((void**)&a,     g_a);
    cudaGetSymbolAddress((void**)&a_hp,  g_a_hp);
    cudaGetSymbolAddress((void**)&h_sum, g_h_sum);
    cudaGetSymbolAddress((void**)&wiha,  g_W_ih_a);
    cudaGetSymbolAddress((void**)&whha,  g_W_hh_a);
    cudaGetSymbolAddress((void**)&wouta, g_W_out_a);
    cudaGetSymbolAddress((void**)&wsum,  g_W_sum);
    cudaGetSymbolAddress((void**)&wihhp, g_W_ih_hp);
    cudaGetSymbolAddress((void**)&whhhp, g_W_hh_hp);
    cudaGetSymbolAddress((void**)&wouthp, g_W_out_hp);

    convert_kernel<<<4096, 256>>>(W_ih_a, W_hh_a, W_out_a, W_sum, W_ih_hp, W_hh_hp, W_out_hp);
    init_kernel<<<(HHP + 255) / 256, 256>>>(x_a, x_hp);

    for (int s = 0; s < DEPTH; ++s) {
        const int pp = s & 1;
        float* hA_in   = h_a + pp * HA;
        float* hA_out  = h_a + (pp ^ 1) * HA;
        float* cA_in   = c_a + pp * HA;
        float* cA_out  = c_a + (pp ^ 1) * HA;
        float* cHP_in  = c_hp + pp * HHP;
        float* cHP_out = c_hp + (pp ^ 1) * HHP;

        k1_kernel<<<HA / 2 + HS / 4, 256>>>(wiha, whha, b_ih_a, b_hh_a,
                                            a, hA_in, cA_in, hA_out, cA_out,
                                            wsum, b_sum, h_hp, h_sum);
        outsoft_kernel<<<16, 256>>>(wouta, b_out_a, hA_out, HA, a, out + s * V);
        k3_kernel<<<HHP / 2, 256>>>(wihhp, whhhp, b_ih_hp, b_hh_hp,
                                    a, a_hp, cHP_in, hA_out, h_sum, h_hp, cHP_out);
        outsoft_kernel<<<16, 256>>>(wouthp, b_out_hp, h_hp, HHP, a_hp,
                                    out + DEPTH * V + s * V);
    }
}

// round 3
// speedup vs baseline: 1.9009x; 1.5707x over previous
#include <cuda_runtime.h>
#include <cuda_fp16.h>
#include <math.h>

#define V    256
#define HA   2048
#define HHP  4096
#define HS   2048
#define DEPTH 12
#define NB   148
#define NT   1024

// ---------------- fp16 weight storage ----------------
__device__ __align__(16) __half g_W_ih_a[4 * HA * V];
__device__ __align__(16) __half g_W_hh_a[4 * HA * HA];
__device__ __align__(16) __half g_W_out_a[V * HA];
__device__ __align__(16) __half g_W_sum[HS * HHP];
__device__ __align__(16) __half g_W_ih_hp[4 * HHP * (2 * V)];
__device__ __align__(16) __half g_W_hh_hp[4 * HHP * HHP];
__device__ __align__(16) __half g_W_out_hp[V * HHP];

// ---------------- persistent state ----------------
__device__ __align__(16) float g_h_a[2][HA];
__device__ __align__(16) float g_c_a[2][HA];
__device__ __align__(16) float g_c_hp[2][HHP];
__device__ __align__(16) float g_h_hp[HHP];
__device__ __align__(16) float g_a[V];
__device__ __align__(16) float g_a_hp[V];
__device__ __align__(16) float g_h_sum[HS];
__device__ __align__(16) float g_logits_a[V];
__device__ __align__(16) float g_logits_hp[V];

__device__ unsigned g_bar_count = 0;
__device__ unsigned g_bar_gen = 0;

__device__ __forceinline__ float sigm(float x) { return 1.f / (1.f + expf(-x)); }

__device__ __forceinline__ float wred(float v) {
    #pragma unroll
    for (int o = 16; o; o >>= 1) v += __shfl_xor_sync(0xffffffffu, v, o);
    return v;
}

// lane-strided partial dot: fp16 weights (int4 = 8 halves, streaming) vs fp32 x in smem
__device__ __forceinline__ float wpart(const __half* __restrict__ W,
                                       const float* __restrict__ sx,
                                       int C8, int lane) {
    const int4* __restrict__ W4 = (const int4*)W;
    const float4* __restrict__ x4 = (const float4*)sx;
    float s = 0.f;
    #pragma unroll 4
    for (int t = lane; t < C8; t += 32) {
        int4 w = __ldcs(W4 + t);
        float4 xa = x4[2 * t], xb = x4[2 * t + 1];
        float2 w0 = __half22float2(*(__half2*)&w.x);
        float2 w1 = __half22float2(*(__half2*)&w.y);
        float2 w2 = __half22float2(*(__half2*)&w.z);
        float2 w3 = __half22float2(*(__half2*)&w.w);
        s = fmaf(w0.x, xa.x, s); s = fmaf(w0.y, xa.y, s);
        s = fmaf(w1.x, xa.z, s); s = fmaf(w1.y, xa.w, s);
        s = fmaf(w2.x, xb.x, s); s = fmaf(w2.y, xb.y, s);
        s = fmaf(w3.x, xb.z, s); s = fmaf(w3.y, xb.w, s);
    }
    return s;
}

// ---------------- fp32 -> fp16 weight conversion ----------------
__global__ void convert_kernel(const float* __restrict__ s0, const float* __restrict__ s1,
                               const float* __restrict__ s2, const float* __restrict__ s3,
                               const float* __restrict__ s4, const float* __restrict__ s5,
                               const float* __restrict__ s6) {
    const size_t n0 = 4ull * HA * V, n1 = 4ull * HA * HA, n2 = (size_t)V * HA,
                 n3 = (size_t)HS * HHP, n4 = 4ull * HHP * 2 * V, n5 = 4ull * HHP * HHP,
                 n6 = (size_t)V * HHP;
    const size_t tot4 = (n0 + n1 + n2 + n3 + n4 + n5 + n6) / 4;
    for (size_t i4 = blockIdx.x * (size_t)blockDim.x + threadIdx.x; i4 < tot4;
         i4 += (size_t)gridDim.x * blockDim.x) {
        size_t i = i4 * 4;
        const float* s; __half* d;
        if (i < n0)              { s = s0; d = g_W_ih_a; }
        else if ((i -= n0) < n1) { s = s1; d = g_W_hh_a; }
        else if ((i -= n1) < n2) { s = s2; d = g_W_out_a; }
        else if ((i -= n2) < n3) { s = s3; d = g_W_sum; }
        else if ((i -= n3) < n4) { s = s4; d = g_W_ih_hp; }
        else if ((i -= n4) < n5) { s = s5; d = g_W_hh_hp; }
        else                     { i -= n5; s = s6; d = g_W_out_hp; }
        float4 v = __ldcs((const float4*)(s + i));
        __half2 lo = __floats2half2_rn(v.x, v.y);
        __half2 hi = __floats2half2_rn(v.z, v.w);
        uint2 u = make_uint2(*(unsigned*)&lo, *(unsigned*)&hi);
        __stcs((uint2*)(d + i), u);
    }
}

// ---------------- persistent decoder kernel ----------------
#define GSYNC() do {                                                         \
    __syncthreads();                                                         \
    ++nb;                                                                    \
    if (tid == 0) {                                                          \
        __threadfence();                                                     \
        if (atomicAdd(&g_bar_count, 1u) == NB - 1) {                         \
            atomicExch(&g_bar_count, 0u);                                    \
            __threadfence();                                                 \
            atomicAdd(&g_bar_gen, 1u);                                       \
        } else {                                                             \
            while ((int)(*(volatile unsigned*)&g_bar_gen - (gen0 + nb)) < 0) {} \
        }                                                                    \
        __threadfence();                                                     \
    }                                                                        \
    __syncthreads();                                                         \
} while (0)

__global__ __launch_bounds__(NT, 1) void persist_kernel(
    const float* __restrict__ xa, const float* __restrict__ xhp,
    const float* __restrict__ biha, const float* __restrict__ bhha,
    const float* __restrict__ bouta, const float* __restrict__ bsum,
    const float* __restrict__ bihhp, const float* __restrict__ bhhhp,
    const float* __restrict__ bouthp, float* __restrict__ out) {
    __shared__ float sbuf[6400];
    __shared__ float sgates[128];
    __shared__ float sred[32];
    __shared__ float sbc[2];
    __shared__ unsigned s_gen0;

    const int tid = threadIdx.x, lane = tid & 31, warp = tid >> 5;
    const int b = blockIdx.x;
    float4* sb4 = (float4*)sbuf;

    if (tid == 0) s_gen0 = atomicAdd(&g_bar_gen, 0u);
    __syncthreads();
    const unsigned gen0 = s_gen0;
    unsigned nb = 0;

    // ---- init state ----
    {
        int gt = b * NT + tid;
        if (gt < HA)  { g_h_a[0][gt] = xa[gt];  g_c_a[0][gt] = 0.f; }
        if (gt < HHP) { g_h_hp[gt]   = xhp[gt]; g_c_hp[0][gt] = 0.f; }
        if (gt < V)   { g_a[gt] = 1.f / V; g_a_hp[gt] = 1.f / V; }
    }
    GSYNC();

    const int uA0 = (b * HA) / NB,  uA1 = ((b + 1) * HA) / NB;
    const int rS0 = (b * HS) / NB,  rS1 = ((b + 1) * HS) / NB;
    const int uH0 = (b * HHP) / NB, uH1 = ((b + 1) * HHP) / NB;
    const int rO0 = (b * V) / NB,   rO1 = ((b + 1) * V) / NB;

    for (int s = 0; s < DEPTH; ++s) {
        const int pp = s & 1;
        const float* hA_in  = g_h_a[pp];   float* hA_out  = g_h_a[pp ^ 1];
        const float* cA_in  = g_c_a[pp];   float* cA_out  = g_c_a[pp ^ 1];
        const float* cHP_in = g_c_hp[pp];  float* cHP_out = g_c_hp[pp ^ 1];

        // =============== phase A: arch LSTM + summarizer ===============
        for (int t = tid; t < 64;   t += NT) sb4[t]       = __ldcg((const float4*)g_a + t);
        for (int t = tid; t < 512;  t += NT) sb4[64 + t]  = __ldcg((const float4*)hA_in + t);
        for (int t = tid; t < 1024; t += NT) sb4[576 + t] = __ldcg((const float4*)g_h_hp + t);
        __syncthreads();

        const int nuA = uA1 - uA0, nrA = nuA * 4;
        for (int r = warp; r < nrA; r += 32) {
            int u = r >> 2, g = r & 3;
            size_t row = (size_t)(g * HA + uA0 + u);
            float p = wpart(g_W_ih_a + row * V, sbuf, V / 8, lane)
                    + wpart(g_W_hh_a + row * HA, sbuf + V, HA / 8, lane);
            p = wred(p);
            if (lane == 0) sgates[r] = p;
        }
        const int nrS = rS1 - rS0;
        for (int r = warp; r < nrS; r += 32) {
            int row = rS0 + r;
            float p = wpart(g_W_sum + (size_t)row * HHP, sbuf + 2304, HHP / 8, lane);
            p = wred(p);
            if (lane == 0) g_h_sum[row] = fmaxf(p + __ldg(bsum + row), 0.f);
        }
        __syncthreads();
        for (int u = tid; u < nuA; u += NT) {
            int j = uA0 + u;
            float gi = sigm(sgates[u * 4 + 0] + __ldg(biha + j)          + __ldg(bhha + j));
            float gf = sigm(sgates[u * 4 + 1] + __ldg(biha + HA + j)     + __ldg(bhha + HA + j));
            float gg = tanhf(sgates[u * 4 + 2] + __ldg(biha + 2 * HA + j) + __ldg(bhha + 2 * HA + j));
            float go = sigm(sgates[u * 4 + 3] + __ldg(biha + 3 * HA + j) + __ldg(bhha + 3 * HA + j));
            float cn = gf * __ldcg(cA_in + j) + gi * gg;
            cA_out[j] = cn;
            hA_out[j] = go * tanhf(cn);
        }
        GSYNC();

        // =============== phase B: logits_a = hA_out @ W_out_a^T + b ===============
        for (int row = rO0; row < rO1; ++row) {
            float p = 0.f;
            if (tid < HA / 8) {
                int4 w = __ldcs((const int4*)(g_W_out_a + (size_t)row * HA) + tid);
                float4 xa4 = __ldcg((const float4*)hA_out + 2 * tid);
                float4 xb4 = __ldcg((const float4*)hA_out + 2 * tid + 1);
                float2 w0 = __half22float2(*(__half2*)&w.x);
                float2 w1 = __half22float2(*(__half2*)&w.y);
                float2 w2 = __half22float2(*(__half2*)&w.z);
                float2 w3 = __half22float2(*(__half2*)&w.w);
                p = fmaf(w0.x, xa4.x, fmaf(w0.y, xa4.y, fmaf(w1.x, xa4.z, fmaf(w1.y, xa4.w,
                    fmaf(w2.x, xb4.x, fmaf(w2.y, xb4.y, fmaf(w3.x, xb4.z, w3.y * xb4.w)))))));
            }
            p = wred(p);
            if (lane == 0) sred[warp] = p;
            __syncthreads();
            if (warp == 0) {
                float v = sred[lane];
                v = wred(v);
                if (lane == 0) g_logits_a[row] = v + __ldg(bouta + row);
            }
            __syncthreads();
        }
        GSYNC();

        // =============== phase C: softmax(logits_a) -> a ; hp LSTM ===============
        {
            float lv = 0.f;
            if (tid < V) {
                lv = __ldcg(g_logits_a + tid);
                float m = lv;
                #pragma unroll
                for (int o = 16; o; o >>= 1) m = fmaxf(m, __shfl_xor_sync(0xffffffffu, m, o));
                if (lane == 0) sred[warp] = m;
            }
            __syncthreads();
            if (tid == 0) {
                float m = sred[0];
                #pragma unroll
                for (int k = 1; k < 8; ++k) m = fmaxf(m, sred[k]);
                sbc[0] = m;
            }
            __syncthreads();
            float ev = 0.f;
            if (tid < V) {
                ev = expf(lv - sbc[0]);
                float ss = wred(ev);
                if (lane == 0) sred[warp] = ss;
            }
            __syncthreads();
            if (tid < V) {
                float bs = sred[0] + sred[1] + sred[2] + sred[3]
                         + sred[4] + sred[5] + sred[6] + sred[7];
                float r = ev / bs;
                sbuf[tid] = r;
                if (b == 0) { g_a[tid] = r; out[s * V + tid] = r; }
            }
        }
        for (int t = tid; t < 64;   t += NT) sb4[64 + t]  = __ldcg((const float4*)g_a_hp + t);
        for (int t = tid; t < 1024; t += NT) sb4[128 + t] = __ldcg((const float4*)cHP_in + t);
        __syncthreads();

        const int nuH = uH1 - uH0, nrH = nuH * 4;
        for (int r = warp; r < nrH; r += 32) {
            int u = r >> 2, g = r & 3;
            size_t row = (size_t)(g * HHP + uH0 + u);
            float p = wpart(g_W_ih_hp + row * (2 * V), sbuf, (2 * V) / 8, lane)
                    + wpart(g_W_hh_hp + row * HHP, sbuf + 2 * V, HHP / 8, lane);
            p = wred(p);
            if (lane == 0) sgates[r] = p;
        }
        __syncthreads();
        for (int u = tid; u < nuH; u += NT) {
            int j = uH0 + u;
            float gi = sigm(sgates[u * 4 + 0] + __ldg(bihhp + j)           + __ldg(bhhhp + j));
            float gf = sigm(sgates[u * 4 + 1] + __ldg(bihhp + HHP + j)     + __ldg(bhhhp + HHP + j));
            float gg = tanhf(sgates[u * 4 + 2] + __ldg(bihhp + 2 * HHP + j) + __ldg(bhhhp + 2 * HHP + j));
            float go = sigm(sgates[u * 4 + 3] + __ldg(bihhp + 3 * HHP + j) + __ldg(bhhhp + 3 * HHP + j));
            float cold = (j < HA) ? __ldcg(hA_out + j) : __ldcg(g_h_sum + (j - HA));
            float cn = gf * cold + gi * gg;
            cHP_out[j] = cn;
            g_h_hp[j] = go * tanhf(cn);
        }
        GSYNC();

        // =============== phase D: logits_hp ===============
        for (int row = rO0; row < rO1; ++row) {
            float p = 0.f;
            if (tid < HHP / 8) {
                int4 w = __ldcs((const int4*)(g_W_out_hp + (size_t)row * HHP) + tid);
                float4 xa4 = __ldcg((const float4*)g_h_hp + 2 * tid);
                float4 xb4 = __ldcg((const float4*)g_h_hp + 2 * tid + 1);
                float2 w0 = __half22float2(*(__half2*)&w.x);
                float2 w1 = __half22float2(*(__half2*)&w.y);
                float2 w2 = __half22float2(*(__half2*)&w.z);
                float2 w3 = __half22float2(*(__half2*)&w.w);
                p = fmaf(w0.x, xa4.x, fmaf(w0.y, xa4.y, fmaf(w1.x, xa4.z, fmaf(w1.y, xa4.w,
                    fmaf(w2.x, xb4.x, fmaf(w2.y, xb4.y, fmaf(w3.x, xb4.z, w3.y * xb4.w)))))));
            }
            p = wred(p);
            if (lane == 0) sred[warp] = p;
            __syncthreads();
            if (warp == 0) {
                float v = sred[lane];
                v = wred(v);
                if (lane == 0) g_logits_hp[row] = v + __ldg(bouthp + row);
            }
            __syncthreads();
        }
        GSYNC();

        // block 0: softmax(logits_hp) -> g_a_hp + output row (consumed 2+ barriers later)
        if (b == 0) {
            float lv = 0.f;
            if (tid < V) {
                lv = __ldcg(g_logits_hp + tid);
                float m = lv;
                #pragma unroll
                for (int o = 16; o; o >>= 1) m = fmaxf(m, __shfl_xor_sync(0xffffffffu, m, o));
                if (lane == 0) sred[warp] = m;
            }
            __syncthreads();
            if (tid == 0) {
                float m = sred[0];
                #pragma unroll
                for (int k = 1; k < 8; ++k) m = fmaxf(m, sred[k]);
                sbc[0] = m;
            }
            __syncthreads();
            float ev = 0.f;
            if (tid < V) {
                ev = expf(lv - sbc[0]);
                float ss = wred(ev);
                if (lane == 0) sred[warp] = ss;
            }
            __syncthreads();
            if (tid < V) {
                float bs = sred[0] + sred[1] + sred[2] + sred[3]
                         + sred[4] + sred[5] + sred[6] + sred[7];
                float r = ev / bs;
                g_a_hp[tid] = r;
                out[DEPTH * V + s * V + tid] = r;
            }
            __syncthreads();
        }
    }
}

// ---------------- launch ----------------
extern "C" void kernel_launch(void* const* d_in, const int* in_sizes, int n_in,
                              void* d_out, int out_size) {
    const float* x_a      = (const float*)d_in[0];
    const float* x_hp     = (const float*)d_in[1];
    const float* W_ih_a   = (const float*)d_in[2];
    const float* W_hh_a   = (const float*)d_in[3];
    const float* b_ih_a   = (const float*)d_in[4];
    const float* b_hh_a   = (const float*)d_in[5];
    const float* W_out_a  = (const float*)d_in[6];
    const float* b_out_a  = (const float*)d_in[7];
    const float* W_sum    = (const float*)d_in[8];
    const float* b_sum    = (const float*)d_in[9];
    const float* W_ih_hp  = (const float*)d_in[10];
    const float* W_hh_hp  = (const float*)d_in[11];
    const float* b_ih_hp  = (const float*)d_in[12];
    const float* b_hh_hp  = (const float*)d_in[13];
    const float* W_out_hp = (const float*)d_in[14];
    const float* b_out_hp = (const float*)d_in[15];
    float* out = (float*)d_out;

    convert_kernel<<<4096, 256>>>(W_ih_a, W_hh_a, W_out_a, W_sum, W_ih_hp, W_hh_hp, W_out_hp);
    persist_kernel<<<NB, NT>>>(x_a, x_hp, b_ih_a, b_hh_a, b_out_a, b_sum,
                               b_ih_hp, b_hh_hp, b_out_hp, out);
}

// round 4
// speedup vs baseline: 2.0676x; 1.0877x over previous
#include <cuda_runtime.h>
#include <cuda_fp16.h>
#include <math.h>

#define V    256
#define HA   2048
#define HHP  4096
#define HS   2048
#define DEPTH 12
#define NB   148
#define NT   1024

// ---------------- fp16 weight storage ----------------
__device__ __align__(16) __half g_W_ih_a[4 * HA * V];
__device__ __align__(16) __half g_W_hh_a[4 * HA * HA];
__device__ __align__(16) __half g_W_out_a[V * HA];
__device__ __align__(16) __half g_W_sum[HS * HHP];
__device__ __align__(16) __half g_W_ih_hp[4 * HHP * (2 * V)];
__device__ __align__(16) __half g_W_hh_hp[4 * HHP * HHP];
__device__ __align__(16) __half g_W_out_hp[V * HHP];

// ---------------- persistent state ----------------
__device__ __align__(16) float g_h_a[2][HA];
__device__ __align__(16) float g_c_a[2][HA];
__device__ __align__(16) float g_c_hp[2][HHP];
__device__ __align__(16) float g_h_hp[HHP];
__device__ __align__(16) float g_h_sum[HS];
__device__ __align__(16) float g_logits_a[V];
__device__ __align__(16) float g_logits_hp[V];

__device__ unsigned g_bar_count = 0;
__device__ unsigned g_bar_gen = 0;

__device__ __forceinline__ float sigm(float x) { return 1.f / (1.f + expf(-x)); }

__device__ __forceinline__ float wred(float v) {
    #pragma unroll
    for (int o = 16; o; o >>= 1) v += __shfl_xor_sync(0xffffffffu, v, o);
    return v;
}

// lane-strided partial dot: fp16 weights vs fp16 x (smem), both int4 = 8 halves
template <bool STREAM>
__device__ __forceinline__ float dot8(const __half* __restrict__ W,
                                      const __half* __restrict__ xh,
                                      int n8, int lane) {
    const int4* __restrict__ W4 = (const int4*)W;
    const int4* __restrict__ X4 = (const int4*)xh;
    float s = 0.f;
    #pragma unroll 4
    for (int t = lane; t < n8; t += 32) {
        int4 w = STREAM ? __ldcs(W4 + t) : __ldg(W4 + t);
        int4 x = X4[t];
        float2 w0 = __half22float2(*(__half2*)&w.x), x0 = __half22float2(*(__half2*)&x.x);
        float2 w1 = __half22float2(*(__half2*)&w.y), x1 = __half22float2(*(__half2*)&x.y);
        float2 w2 = __half22float2(*(__half2*)&w.z), x2 = __half22float2(*(__half2*)&x.z);
        float2 w3 = __half22float2(*(__half2*)&w.w), x3 = __half22float2(*(__half2*)&x.w);
        s = fmaf(w0.x, x0.x, s); s = fmaf(w0.y, x0.y, s);
        s = fmaf(w1.x, x1.x, s); s = fmaf(w1.y, x1.y, s);
        s = fmaf(w2.x, x2.x, s); s = fmaf(w2.y, x2.y, s);
        s = fmaf(w3.x, x3.x, s); s = fmaf(w3.y, x3.y, s);
    }
    return s;
}

// ---------------- fp32 -> fp16 weight conversion ----------------
__global__ void convert_kernel(const float* __restrict__ s0, const float* __restrict__ s1,
                               const float* __restrict__ s2, const float* __restrict__ s3,
                               const float* __restrict__ s4, const float* __restrict__ s5,
                               const float* __restrict__ s6) {
    const size_t n0 = 4ull * HA * V, n1 = 4ull * HA * HA, n2 = (size_t)V * HA,
                 n3 = (size_t)HS * HHP, n4 = 4ull * HHP * 2 * V, n5 = 4ull * HHP * HHP,
                 n6 = (size_t)V * HHP;
    const size_t tot4 = (n0 + n1 + n2 + n3 + n4 + n5 + n6) / 4;
    for (size_t i4 = blockIdx.x * (size_t)blockDim.x + threadIdx.x; i4 < tot4;
         i4 += (size_t)gridDim.x * blockDim.x) {
        size_t i = i4 * 4;
        const float* s; __half* d;
        if (i < n0)              { s = s0; d = g_W_ih_a; }
        else if ((i -= n0) < n1) { s = s1; d = g_W_hh_a; }
        else if ((i -= n1) < n2) { s = s2; d = g_W_out_a; }
        else if ((i -= n2) < n3) { s = s3; d = g_W_sum; }
        else if ((i -= n3) < n4) { s = s4; d = g_W_ih_hp; }
        else if ((i -= n4) < n5) { s = s5; d = g_W_hh_hp; }
        else                     { i -= n5; s = s6; d = g_W_out_hp; }
        float4 v = __ldcs((const float4*)(s + i));
        __half2 lo = __floats2half2_rn(v.x, v.y);
        __half2 hi = __floats2half2_rn(v.z, v.w);
        uint2 u = make_uint2(*(unsigned*)&lo, *(unsigned*)&hi);
        __stcs((uint2*)(d + i), u);
    }
}

// ---------------- persistent decoder ----------------
#define GSYNC() do {                                                         \
    __syncthreads();                                                         \
    ++nb;                                                                    \
    if (tid == 0) {                                                          \
        __threadfence();                                                     \
        if (atomicAdd(&g_bar_count, 1u) == NB - 1) {                         \
            atomicExch(&g_bar_count, 0u);                                    \
            __threadfence();                                                 \
            atomicAdd(&g_bar_gen, 1u);                                       \
        } else {                                                             \
            while ((int)(*(volatile unsigned*)&g_bar_gen - (gen0 + nb)) < 0) {} \
        }                                                                    \
        __threadfence();                                                     \
    }                                                                        \
    __syncthreads();                                                         \
} while (0)

__device__ __forceinline__ void stage_half(const float* __restrict__ g,
                                           __half* __restrict__ sh, int n, int tid) {
    for (int t = tid; t < n / 8; t += NT) {
        float4 v1 = __ldcg((const float4*)g + 2 * t);
        float4 v2 = __ldcg((const float4*)g + 2 * t + 1);
        __half2 h0 = __floats2half2_rn(v1.x, v1.y);
        __half2 h1 = __floats2half2_rn(v1.z, v1.w);
        __half2 h2 = __floats2half2_rn(v2.x, v2.y);
        __half2 h3 = __floats2half2_rn(v2.z, v2.w);
        int4 o;
        o.x = *(int*)&h0; o.y = *(int*)&h1; o.z = *(int*)&h2; o.w = *(int*)&h3;
        ((int4*)sh)[t] = o;
    }
}

// redundant block softmax over V logits; outH always, outF (global row) if non-null
__device__ __forceinline__ void block_softmax(const float* __restrict__ gl,
                                              float* __restrict__ outF,
                                              __half* __restrict__ outH,
                                              float* sred, float* sbc,
                                              int tid, int lane, int warp) {
    float lv = 0.f, ev = 0.f;
    if (tid < V) {
        lv = __ldcg(gl + tid);
        float m = lv;
        #pragma unroll
        for (int o = 16; o; o >>= 1) m = fmaxf(m, __shfl_xor_sync(0xffffffffu, m, o));
        if (lane == 0) sred[warp] = m;
    }
    __syncthreads();
    if (tid == 0) {
        float m = sred[0];
        #pragma unroll
        for (int k = 1; k < 8; ++k) m = fmaxf(m, sred[k]);
        sbc[0] = m;
    }
    __syncthreads();
    if (tid < V) {
        ev = expf(lv - sbc[0]);
        float ss = wred(ev);
        if (lane == 0) sred[warp] = ss;
    }
    __syncthreads();
    if (tid < V) {
        float bs = sred[0] + sred[1] + sred[2] + sred[3]
                 + sred[4] + sred[5] + sred[6] + sred[7];
        float r = ev / bs;
        outH[tid] = __float2half(r);
        if (outF) outF[tid] = r;
    }
    __syncthreads();
}

// this block's logit rows: fp16 W (cached) dot fp32 x (global)
__device__ __forceinline__ void logits_rows(const __half* __restrict__ W,
                                            const float* __restrict__ bias,
                                            const float* __restrict__ x, int C,
                                            float* __restrict__ gl, int r0, int r1,
                                            float* sred, int tid, int lane, int warp) {
    for (int row = r0; row < r1; ++row) {
        float p = 0.f;
        if (tid < C / 8) {
            int4 w = __ldg((const int4*)(W + (size_t)row * C) + tid);
            float4 xa4 = __ldcg((const float4*)x + 2 * tid);
            float4 xb4 = __ldcg((const float4*)x + 2 * tid + 1);
            float2 w0 = __half22float2(*(__half2*)&w.x);
            float2 w1 = __half22float2(*(__half2*)&w.y);
            float2 w2 = __half22float2(*(__half2*)&w.z);
            float2 w3 = __half22float2(*(__half2*)&w.w);
            p = fmaf(w0.x, xa4.x, fmaf(w0.y, xa4.y, fmaf(w1.x, xa4.z, fmaf(w1.y, xa4.w,
                fmaf(w2.x, xb4.x, fmaf(w2.y, xb4.y, fmaf(w3.x, xb4.z, w3.y * xb4.w)))))));
        }
        p = wred(p);
        if (lane == 0) sred[warp] = p;
        __syncthreads();
        if (warp == 0) {
            float v = sred[lane];
            v = wred(v);
            if (lane == 0) gl[row] = v + __ldg(bias + row);
        }
        __syncthreads();
    }
}

__global__ __launch_bounds__(NT, 1) void persist_kernel(
    const float* __restrict__ xa, const float* __restrict__ xhp,
    const float* __restrict__ biha, const float* __restrict__ bhha,
    const float* __restrict__ bouta, const float* __restrict__ bsum,
    const float* __restrict__ bihhp, const float* __restrict__ bhhhp,
    const float* __restrict__ bouthp, float* __restrict__ out) {
    __shared__ __align__(16) __half s_a[V];
    __shared__ __align__(16) __half s_ahp[V];
    __shared__ __align__(16) __half s_hA[HA];
    __shared__ __align__(16) __half s_hhp[HHP];
    __shared__ __align__(16) __half s_chp[HHP];
    __shared__ float pA[112], pS[56], pH[448], pIHa[112], pIHb[112];
    __shared__ float sred[32], sbc[2];
    __shared__ unsigned s_gen0;

    const int tid = threadIdx.x, lane = tid & 31, warp = tid >> 5;
    const int b = blockIdx.x;

    if (tid == 0) s_gen0 = atomicAdd(&g_bar_gen, 0u);
    __syncthreads();
    const unsigned gen0 = s_gen0;
    unsigned nb = 0;

    // ---- init global state + local soft one-hots ----
    {
        int gt = b * NT + tid;
        if (gt < HA)  { g_h_a[0][gt] = xa[gt];  g_c_a[0][gt] = 0.f; }
        if (gt < HHP) { g_h_hp[gt]   = xhp[gt]; g_c_hp[0][gt] = 0.f; }
        if (tid < V) { s_a[tid] = __float2half(1.f / V); s_ahp[tid] = __float2half(1.f / V); }
    }
    GSYNC();

    const int uA0 = (b * HA) / NB,  uA1 = ((b + 1) * HA) / NB;
    const int rS0 = (b * HS) / NB,  rS1 = ((b + 1) * HS) / NB;
    const int uH0 = (b * HHP) / NB, uH1 = ((b + 1) * HHP) / NB;
    const int rO0 = (b * V) / NB,   rO1 = ((b + 1) * V) / NB;
    const int nuA = uA1 - uA0, nrA = 4 * nuA;
    const int nrS = rS1 - rS0;
    const int nuH = uH1 - uH0, nrH = 4 * nuH;
    const int nA2 = nrA * 2, nS4 = nrS * 4, nH4 = nrH * 4;
    const int ntot = nA2 + nS4 + nH4;

    for (int s = 0; s < DEPTH; ++s) {
        const int pp = s & 1;
        const float* hA_in  = g_h_a[pp];   float* hA_out  = g_h_a[pp ^ 1];
        const float* cA_in  = g_c_a[pp];   float* cA_out  = g_c_a[pp ^ 1];
        const float* cHP_in = g_c_hp[pp];  float* cHP_out = g_c_hp[pp ^ 1];

        // ============ P1: arch LSTM + summarizer + W_hh_hp partials (all prev-step inputs) ============
        stage_half(hA_in,  s_hA,  HA,  tid);
        stage_half(g_h_hp, s_hhp, HHP, tid);
        stage_half(cHP_in, s_chp, HHP, tid);
        __syncthreads();

        for (int t = warp; t < ntot; t += 32) {
            float p;
            if (t < nA2) {
                int r = t >> 1, c = t & 1;
                int u = r >> 2, g = r & 3;
                size_t row = (size_t)(g * HA + uA0 + u);
                if (c == 0)
                    p = dot8<false>(g_W_ih_a + row * V, s_a, V / 8, lane)
                      + dot8<false>(g_W_hh_a + row * HA, s_hA, 128, lane);
                else
                    p = dot8<false>(g_W_hh_a + row * HA + 1024, s_hA + 1024, 128, lane);
                p = wred(p);
                if (lane == 0) pA[t] = p;
            } else if (t < nA2 + nS4) {
                int t2 = t - nA2, r = t2 >> 2, c = t2 & 3;
                size_t row = (size_t)(rS0 + r);
                p = dot8<false>(g_W_sum + row * HHP + c * 1024, s_hhp + c * 1024, 128, lane);
                p = wred(p);
                if (lane == 0) pS[t2] = p;
            } else {
                int t3 = t - nA2 - nS4, r = t3 >> 2, c = t3 & 3;
                int u = r >> 2, g = r & 3;
                size_t row = (size_t)(g * HHP + uH0 + u);
                p = dot8<true>(g_W_hh_hp + row * HHP + c * 1024, s_chp + c * 1024, 128, lane);
                p = wred(p);
                if (lane == 0) pH[t3] = p;
            }
        }
        __syncthreads();
        for (int u = tid; u < nuA; u += NT) {
            int j = uA0 + u;
            float gv[4];
            #pragma unroll
            for (int g = 0; g < 4; ++g)
                gv[g] = pA[(u * 4 + g) * 2] + pA[(u * 4 + g) * 2 + 1]
                      + __ldg(biha + g * HA + j) + __ldg(bhha + g * HA + j);
            float gi = sigm(gv[0]), gf = sigm(gv[1]), gg = tanhf(gv[2]), go = sigm(gv[3]);
            float cn = gf * __ldcg(cA_in + j) + gi * gg;
            cA_out[j] = cn;
            hA_out[j] = go * tanhf(cn);
        }
        for (int r = tid; r < nrS; r += NT) {
            int row = rS0 + r;
            float v = pS[r * 4] + pS[r * 4 + 1] + pS[r * 4 + 2] + pS[r * 4 + 3]
                    + __ldg(bsum + row);
            g_h_sum[row] = fmaxf(v, 0.f);
        }
        GSYNC();

        // ============ P2: a_hp(s-1) softmax (redundant), logits_a, ih·a_hp partials ============
        if (s > 0)
            block_softmax(g_logits_hp, (b == 0) ? (out + DEPTH * V + (s - 1) * V) : nullptr,
                          s_ahp, sred, sbc, tid, lane, warp);
        logits_rows(g_W_out_a, bouta, hA_out, HA, g_logits_a, rO0, rO1,
                    sred, tid, lane, warp);
        for (int r = warp; r < nrH; r += 32) {
            int u = r >> 2, g = r & 3;
            size_t row = (size_t)(g * HHP + uH0 + u);
            float p = dot8<false>(g_W_ih_hp + row * (2 * V) + V, s_ahp, V / 8, lane);
            p = wred(p);
            if (lane == 0) pIHb[r] = p;
        }
        GSYNC();

        // ============ P3: a(s) softmax (redundant), ih·a partials, hp elementwise ============
        block_softmax(g_logits_a, (b == 0) ? (out + s * V) : nullptr,
                      s_a, sred, sbc, tid, lane, warp);
        for (int r = warp; r < nrH; r += 32) {
            int u = r >> 2, g = r & 3;
            size_t row = (size_t)(g * HHP + uH0 + u);
            float p = dot8<false>(g_W_ih_hp + row * (2 * V), s_a, V / 8, lane);
            p = wred(p);
            if (lane == 0) pIHa[r] = p;
        }
        __syncthreads();
        for (int u = tid; u < nuH; u += NT) {
            int j = uH0 + u;
            float gv[4];
            #pragma unroll
            for (int g = 0; g < 4; ++g) {
                int r = u * 4 + g;
                gv[g] = pH[r * 4] + pH[r * 4 + 1] + pH[r * 4 + 2] + pH[r * 4 + 3]
                      + pIHa[r] + pIHb[r]
                      + __ldg(bihhp + g * HHP + j) + __ldg(bhhhp + g * HHP + j);
            }
            float gi = sigm(gv[0]), gf = sigm(gv[1]), gg = tanhf(gv[2]), go = sigm(gv[3]);
            float cold = (j < HA) ? __ldcg(hA_out + j) : __ldcg(g_h_sum + (j - HA));
            float cn = gf * cold + gi * gg;
            cHP_out[j] = cn;
            g_h_hp[j] = go * tanhf(cn);
        }
        GSYNC();

        // ============ P4: logits_hp ============
        logits_rows(g_W_out_hp, bouthp, g_h_hp, HHP, g_logits_hp, rO0, rO1,
                    sred, tid, lane, warp);
        GSYNC();
    }

    // epilogue: final a_hp(11)
    if (b == 0)
        block_softmax(g_logits_hp, out + DEPTH * V + (DEPTH - 1) * V,
                      s_ahp, sred, sbc, tid, lane, warp);
}

// ---------------- launch ----------------
extern "C" void kernel_launch(void* const* d_in, const int* in_sizes, int n_in,
                              void* d_out, int out_size) {
    const float* x_a      = (const float*)d_in[0];
    const float* x_hp     = (const float*)d_in[1];
    const float* W_ih_a   = (const float*)d_in[2];
    const float* W_hh_a   = (const float*)d_in[3];
    const float* b_ih_a   = (const float*)d_in[4];
    const float* b_hh_a   = (const float*)d_in[5];
    const float* W_out_a  = (const float*)d_in[6];
    const float* b_out_a  = (const float*)d_in[7];
    const float* W_sum    = (const float*)d_in[8];
    const float* b_sum    = (const float*)d_in[9];
    const float* W_ih_hp  = (const float*)d_in[10];
    const float* W_hh_hp  = (const float*)d_in[11];
    const float* b_ih_hp  = (const float*)d_in[12];
    const float* b_hh_hp  = (const float*)d_in[13];
    const float* W_out_hp = (const float*)d_in[14];
    const float* b_out_hp = (const float*)d_in[15];
    float* out = (float*)d_out;

    convert_kernel<<<4096, 256>>>(W_ih_a, W_hh_a, W_out_a, W_sum, W_ih_hp, W_hh_hp, W_out_hp);
    persist_kernel<<<NB, NT>>>(x_a, x_hp, b_ih_a, b_hh_a, b_out_a, b_sum,
                               b_ih_hp, b_hh_hp, b_out_hp, out);
}

// round 7
// speedup vs baseline: 2.2402x; 1.0835x over previous
#include <cuda_runtime.h>
#include <cuda_fp16.h>
#include <math.h>

#define V    256
#define HA   2048
#define HHP  4096
#define HS   2048
#define DEPTH 12
#define NB   148
#define NT   1024

// ---------------- fp16 weight storage ----------------
__device__ __align__(16) __half g_W_ih_a[4 * HA * V];
__device__ __align__(16) __half g_W_hh_a[4 * HA * HA];
__device__ __align__(16) __half g_W_out_a[V * HA];
__device__ __align__(16) __half g_W_sum[HS * HHP];
__device__ __align__(16) __half g_W_ih_hp[4 * HHP * (2 * V)];
__device__ __align__(16) __half g_W_hh_hp[4 * HHP * HHP];
__device__ __align__(16) __half g_W_out_hp[V * HHP];

// ---------------- persistent state ----------------
__device__ __align__(16) float g_h_a[2][HA];
__device__ __align__(16) float g_c_a[2][HA];
__device__ __align__(16) float g_c_hp[2][HHP];
__device__ __align__(16) float g_h_hp[HHP];
__device__ __align__(16) float g_h_sum[HS];
__device__ __align__(16) float g_logits_a[V];
__device__ __align__(16) float g_logits_hp[V];

__device__ unsigned g_bar_count = 0;
__device__ unsigned g_bar_gen = 0;

__device__ __forceinline__ float sigm(float x) { return 1.f / (1.f + expf(-x)); }

__device__ __forceinline__ float wred(float v) {
    #pragma unroll
    for (int o = 16; o; o >>= 1) v += __shfl_xor_sync(0xffffffffu, v, o);
    return v;
}

// lane-strided partial dot: fp16 weights vs fp16 x (smem).
// half2 FMA within an 8-element segment, fp32 accumulation across segments.
template <bool STREAM>
__device__ __forceinline__ float dot8h(const __half* __restrict__ W,
                                       const __half* __restrict__ xh,
                                       int n8, int lane) {
    const int4* __restrict__ W4 = (const int4*)W;
    const int4* __restrict__ X4 = (const int4*)xh;
    float s = 0.f;
    #pragma unroll 4
    for (int t = lane; t < n8; t += 32) {
        int4 w = STREAM ? __ldcs(W4 + t) : __ldg(W4 + t);
        int4 x = X4[t];
        __half2 acc = __hmul2(*(__half2*)&w.x, *(__half2*)&x.x);
        acc = __hfma2(*(__half2*)&w.y, *(__half2*)&x.y, acc);
        acc = __hfma2(*(__half2*)&w.z, *(__half2*)&x.z, acc);
        acc = __hfma2(*(__half2*)&w.w, *(__half2*)&x.w, acc);
        float2 f = __half22float2(acc);
        s += f.x + f.y;
    }
    return s;
}

// ---------------- fp32 -> fp16 weight conversion ----------------
__global__ void convert_kernel(const float* __restrict__ s0, const float* __restrict__ s1,
                               const float* __restrict__ s2, const float* __restrict__ s3,
                               const float* __restrict__ s4, const float* __restrict__ s5,
                               const float* __restrict__ s6) {
    const size_t n0 = 4ull * HA * V, n1 = 4ull * HA * HA, n2 = (size_t)V * HA,
                 n3 = (size_t)HS * HHP, n4 = 4ull * HHP * 2 * V, n5 = 4ull * HHP * HHP,
                 n6 = (size_t)V * HHP;
    const size_t tot4 = (n0 + n1 + n2 + n3 + n4 + n5 + n6) / 4;
    for (size_t i4 = blockIdx.x * (size_t)blockDim.x + threadIdx.x; i4 < tot4;
         i4 += (size_t)gridDim.x * blockDim.x) {
        size_t i = i4 * 4;
        const float* s; __half* d;
        if (i < n0)              { s = s0; d = g_W_ih_a; }
        else if ((i -= n0) < n1) { s = s1; d = g_W_hh_a; }
        else if ((i -= n1) < n2) { s = s2; d = g_W_out_a; }
        else if ((i -= n2) < n3) { s = s3; d = g_W_sum; }
        else if ((i -= n3) < n4) { s = s4; d = g_W_ih_hp; }
        else if ((i -= n4) < n5) { s = s5; d = g_W_hh_hp; }
        else                     { i -= n5; s = s6; d = g_W_out_hp; }
        float4 v = __ldcs((const float4*)(s + i));
        __half2 lo = __floats2half2_rn(v.x, v.y);
        __half2 hi = __floats2half2_rn(v.z, v.w);
        uint2 u = make_uint2(*(unsigned*)&lo, *(unsigned*)&hi);
        __stcs((uint2*)(d + i), u);
    }
}

// ---------------- persistent decoder ----------------
#define GSYNC() do {                                                         \
    __syncthreads();                                                         \
    ++nb;                                                                    \
    if (tid == 0) {                                                          \
        __threadfence();                                                     \
        if (atomicAdd(&g_bar_count, 1u) == NB - 1) {                         \
            atomicExch(&g_bar_count, 0u);                                    \
            __threadfence();                                                 \
            atomicAdd(&g_bar_gen, 1u);                                       \
        } else {                                                             \
            while ((int)(*(volatile unsigned*)&g_bar_gen - (gen0 + nb)) < 0) {} \
        }                                                                    \
        __threadfence();                                                     \
    }                                                                        \
    __syncthreads();                                                         \
} while (0)

__device__ __forceinline__ void stage_half(const float* __restrict__ g,
                                           __half* __restrict__ sh, int n, int tid) {
    for (int t = tid; t < n / 8; t += NT) {
        float4 v1 = __ldcg((const float4*)g + 2 * t);
        float4 v2 = __ldcg((const float4*)g + 2 * t + 1);
        __half2 h0 = __floats2half2_rn(v1.x, v1.y);
        __half2 h1 = __floats2half2_rn(v1.z, v1.w);
        __half2 h2 = __floats2half2_rn(v2.x, v2.y);
        __half2 h3 = __floats2half2_rn(v2.z, v2.w);
        int4 o;
        o.x = *(int*)&h0; o.y = *(int*)&h1; o.z = *(int*)&h2; o.w = *(int*)&h3;
        ((int4*)sh)[t] = o;
    }
}

// redundant block softmax over V logits; outH always, outF (global row) if non-null
__device__ __forceinline__ void block_softmax(const float* __restrict__ gl,
                                              float* __restrict__ outF,
                                              __half* __restrict__ outH,
                                              float* sred, float* sbc,
                                              int tid, int lane, int warp) {
    float lv = 0.f, ev = 0.f;
    if (tid < V) {
        lv = __ldcg(gl + tid);
        float m = lv;
        #pragma unroll
        for (int o = 16; o; o >>= 1) m = fmaxf(m, __shfl_xor_sync(0xffffffffu, m, o));
        if (lane == 0) sred[warp] = m;
    }
    __syncthreads();
    if (tid == 0) {
        float m = sred[0];
        #pragma unroll
        for (int k = 1; k < 8; ++k) m = fmaxf(m, sred[k]);
        sbc[0] = m;
    }
    __syncthreads();
    if (tid < V) {
        ev = expf(lv - sbc[0]);
        float ss = wred(ev);
        if (lane == 0) sred[warp] = ss;
    }
    __syncthreads();
    if (tid < V) {
        float bs = sred[0] + sred[1] + sred[2] + sred[3]
                 + sred[4] + sred[5] + sred[6] + sred[7];
        float r = ev / bs;
        outH[tid] = __float2half(r);
        if (outF) outF[tid] = r;
    }
    __syncthreads();
}

// this block's logit rows: fp16 W (cached) dot fp32 x (global, __ldcg)
__device__ __forceinline__ void logits_rows(const __half* __restrict__ W,
                                            const float* __restrict__ bias,
                                            const float* __restrict__ x, int C,
                                            float* __restrict__ gl, int r0, int r1,
                                            float* sred, int tid, int lane, int warp) {
    for (int row = r0; row < r1; ++row) {
        float p = 0.f;
        if (tid < C / 8) {
            int4 w = __ldg((const int4*)(W + (size_t)row * C) + tid);
            float4 xa4 = __ldcg((const float4*)x + 2 * tid);
            float4 xb4 = __ldcg((const float4*)x + 2 * tid + 1);
            float2 w0 = __half22float2(*(__half2*)&w.x);
            float2 w1 = __half22float2(*(__half2*)&w.y);
            float2 w2 = __half22float2(*(__half2*)&w.z);
            float2 w3 = __half22float2(*(__half2*)&w.w);
            p = fmaf(w0.x, xa4.x, fmaf(w0.y, xa4.y, fmaf(w1.x, xa4.z, fmaf(w1.y, xa4.w,
                fmaf(w2.x, xb4.x, fmaf(w2.y, xb4.y, fmaf(w3.x, xb4.z, w3.y * xb4.w)))))));
        }
        p = wred(p);
        if (lane == 0) sred[warp] = p;
        __syncthreads();
        if (warp == 0) {
            float v = sred[lane];
            v = wred(v);
            if (lane == 0) gl[row] = v + __ldg(bias + row);
        }
        __syncthreads();
    }
}

__global__ __launch_bounds__(NT, 1) void persist_kernel(
    const float* __restrict__ xa, const float* __restrict__ xhp,
    const float* __restrict__ biha, const float* __restrict__ bhha,
    const float* __restrict__ bouta, const float* __restrict__ bsum,
    const float* __restrict__ bihhp, const float* __restrict__ bhhhp,
    const float* __restrict__ bouthp, float* __restrict__ out) {
    __shared__ __align__(16) __half s_a[V];
    __shared__ __align__(16) __half s_ahp[V];
    __shared__ __align__(16) __half s_hA[HA];
    __shared__ __align__(16) __half s_hhp[HHP];
    __shared__ __align__(16) __half s_chp[HHP];
    __shared__ float pA[112], pS[56], pH[448], pL[8], pIHa[112], pIHb[112];
    __shared__ float sred[32], sbc[2];
    __shared__ unsigned s_gen0;

    const int tid = threadIdx.x, lane = tid & 31, warp = tid >> 5;
    const int b = blockIdx.x;

    if (tid == 0) s_gen0 = atomicAdd(&g_bar_gen, 0u);
    __syncthreads();
    const unsigned gen0 = s_gen0;
    unsigned nb = 0;

    // ---- init global state + local soft one-hots ----
    {
        int gt = b * NT + tid;
        if (gt < HA)  { g_h_a[0][gt] = xa[gt];  g_c_a[0][gt] = 0.f; }
        if (gt < HHP) { g_h_hp[gt]   = xhp[gt]; g_c_hp[0][gt] = 0.f; }
        if (tid < V) { s_a[tid] = __float2half(1.f / V); s_ahp[tid] = __float2half(1.f / V); }
    }
    GSYNC();

    const int uA0 = (b * HA) / NB,  uA1 = ((b + 1) * HA) / NB;
    const int rS0 = (b * HS) / NB,  rS1 = ((b + 1) * HS) / NB;
    const int uH0 = (b * HHP) / NB, uH1 = ((b + 1) * HHP) / NB;
    const int rO0 = (b * V) / NB,   rO1 = ((b + 1) * V) / NB;
    const int nuA = uA1 - uA0, nrA = 4 * nuA;
    const int nrS = rS1 - rS0;
    const int nuH = uH1 - uH0, nrH = 4 * nuH;
    const int nrO = rO1 - rO0;
    const int nA2 = nrA * 2, nS4 = nrS * 4, nH4 = nrH * 4, nL4 = nrO * 4;
    const int ntot = nA2 + nS4 + nH4 + nL4;

    for (int s = 0; s < DEPTH; ++s) {
        const int pp = s & 1;
        const float* hA_in  = g_h_a[pp];   float* hA_out  = g_h_a[pp ^ 1];
        const float* cA_in  = g_c_a[pp];   float* cA_out  = g_c_a[pp ^ 1];
        const float* cHP_in = g_c_hp[pp];  float* cHP_out = g_c_hp[pp ^ 1];

        // ==== P1: arch LSTM + summarizer + W_hh_hp partials + logits_hp(s-1) ====
        stage_half(hA_in,  s_hA,  HA,  tid);
        stage_half(g_h_hp, s_hhp, HHP, tid);
        stage_half(cHP_in, s_chp, HHP, tid);
        __syncthreads();

        for (int t = warp; t < ntot; t += 32) {
            float p;
            if (t < nA2) {
                int r = t >> 1, c = t & 1;
                int u = r >> 2, g = r & 3;
                size_t row = (size_t)(g * HA + uA0 + u);
                if (c == 0)
                    p = dot8h<false>(g_W_ih_a + row * V, s_a, V / 8, lane)
                      + dot8h<false>(g_W_hh_a + row * HA, s_hA, 128, lane);
                else
                    p = dot8h<false>(g_W_hh_a + row * HA + 1024, s_hA + 1024, 128, lane);
                p = wred(p);
                if (lane == 0) pA[t] = p;
            } else if (t < nA2 + nS4) {
                int t2 = t - nA2, r = t2 >> 2, c = t2 & 3;
                size_t row = (size_t)(rS0 + r);
                p = dot8h<false>(g_W_sum + row * HHP + c * 1024, s_hhp + c * 1024, 128, lane);
                p = wred(p);
                if (lane == 0) pS[t2] = p;
            } else if (t < nA2 + nS4 + nH4) {
                int t3 = t - nA2 - nS4, r = t3 >> 2, c = t3 & 3;
                int u = r >> 2, g = r & 3;
                size_t row = (size_t)(g * HHP + uH0 + u);
                p = dot8h<true>(g_W_hh_hp + row * HHP + c * 1024, s_chp + c * 1024, 128, lane);
                p = wred(p);
                if (lane == 0) pH[t3] = p;
            } else {
                int t4 = t - nA2 - nS4 - nH4, r = t4 >> 2, c = t4 & 3;
                size_t row = (size_t)(rO0 + r);
                p = dot8h<false>(g_W_out_hp + row * HHP + c * 1024, s_hhp + c * 1024, 128, lane);
                p = wred(p);
                if (lane == 0) pL[t4] = p;
            }
        }
        __syncthreads();
        for (int u = tid; u < nuA; u += NT) {
            int j = uA0 + u;
            float gv[4];
            #pragma unroll
            for (int g = 0; g < 4; ++g)
                gv[g] = pA[(u * 4 + g) * 2] + pA[(u * 4 + g) * 2 + 1]
                      + __ldg(biha + g * HA + j) + __ldg(bhha + g * HA + j);
            float gi = sigm(gv[0]), gf = sigm(gv[1]), gg = tanhf(gv[2]), go = sigm(gv[3]);
            float cn = gf * __ldcg(cA_in + j) + gi * gg;
            cA_out[j] = cn;
            hA_out[j] = go * tanhf(cn);
        }
        for (int r = tid; r < nrS; r += NT) {
            int row = rS0 + r;
            float v = pS[r * 4] + pS[r * 4 + 1] + pS[r * 4 + 2] + pS[r * 4 + 3]
                    + __ldg(bsum + row);
            g_h_sum[row] = fmaxf(v, 0.f);
        }
        for (int r = tid; r < nrO; r += NT) {
            int row = rO0 + r;
            g_logits_hp[row] = pL[r * 4] + pL[r * 4 + 1] + pL[r * 4 + 2] + pL[r * 4 + 3]
                             + __ldg(bouthp + row);
        }
        GSYNC();

        // ==== P2: softmax a_hp(s-1) (redundant), logits_a(s), ih·a_hp partials ====
        if (s > 0)
            block_softmax(g_logits_hp, (b == 0) ? (out + DEPTH * V + (s - 1) * V) : nullptr,
                          s_ahp, sred, sbc, tid, lane, warp);
        logits_rows(g_W_out_a, bouta, hA_out, HA, g_logits_a, rO0, rO1,
                    sred, tid, lane, warp);
        for (int r = warp; r < nrH; r += 32) {
            int u = r >> 2, g = r & 3;
            size_t row = (size_t)(g * HHP + uH0 + u);
            float p = dot8h<false>(g_W_ih_hp + row * (2 * V) + V, s_ahp, V / 8, lane);
            p = wred(p);
            if (lane == 0) pIHb[r] = p;
        }
        GSYNC();

        // ==== P3: softmax a(s) (redundant), ih·a partials, hp elementwise ====
        block_softmax(g_logits_a, (b == 0) ? (out + s * V) : nullptr,
                      s_a, sred, sbc, tid, lane, warp);
        for (int r = warp; r < nrH; r += 32) {
            int u = r >> 2, g = r & 3;
            size_t row = (size_t)(g * HHP + uH0 + u);
            float p = dot8h<false>(g_W_ih_hp + row * (2 * V), s_a, V / 8, lane);
            p = wred(p);
            if (lane == 0) pIHa[r] = p;
        }
        __syncthreads();
        for (int u = tid; u < nuH; u += NT) {
            int j = uH0 + u;
            float gv[4];
            #pragma unroll
            for (int g = 0; g < 4; ++g) {
                int r = u * 4 + g;
                gv[g] = pH[r * 4] + pH[r * 4 + 1] + pH[r * 4 + 2] + pH[r * 4 + 3]
                      + pIHa[r] + pIHb[r]
                      + __ldg(bihhp + g * HHP + j) + __ldg(bhhhp + g * HHP + j);
            }
            float gi = sigm(gv[0]), gf = sigm(gv[1]), gg = tanhf(gv[2]), go = sigm(gv[3]);
            float cold = (j < HA) ? __ldcg(hA_out + j) : __ldcg(g_h_sum + (j - HA));
            float cn = gf * cold + gi * gg;
            cHP_out[j] = cn;
            g_h_hp[j] = go * tanhf(cn);
        }
        GSYNC();
    }

    // ==== epilogue: logits_hp(11) + final softmax ====
    logits_rows(g_W_out_hp, bouthp, g_h_hp, HHP, g_logits_hp, rO0, rO1,
                sred, tid, lane, warp);
    GSYNC();
    if (b == 0)
        block_softmax(g_logits_hp, out + DEPTH * V + (DEPTH - 1) * V,
                      s_ahp, sred, sbc, tid, lane, warp);
}

// ---------------- launch ----------------
extern "C" void kernel_launch(void* const* d_in, const int* in_sizes, int n_in,
                              void* d_out, int out_size) {
    const float* x_a      = (const float*)d_in[0];
    const float* x_hp     = (const float*)d_in[1];
    const float* W_ih_a   = (const float*)d_in[2];
    const float* W_hh_a   = (const float*)d_in[3];
    const float* b_ih_a   = (const float*)d_in[4];
    const float* b_hh_a   = (const float*)d_in[5];
    const float* W_out_a  = (const float*)d_in[6];
    const float* b_out_a  = (const float*)d_in[7];
    const float* W_sum    = (const float*)d_in[8];
    const float* b_sum    = (const float*)d_in[9];
    const float* W_ih_hp  = (const float*)d_in[10];
    const float* W_hh_hp  = (const float*)d_in[11];
    const float* b_ih_hp  = (const float*)d_in[12];
    const float* b_hh_hp  = (const float*)d_in[13];
    const float* W_out_hp = (const float*)d_in[14];
    const float* b_out_hp = (const float*)d_in[15];
    float* out = (float*)d_out;

    convert_kernel<<<4096, 256>>>(W_ih_a, W_hh_a, W_out_a, W_sum, W_ih_hp, W_hh_hp, W_out_hp);
    persist_kernel<<<NB, NT>>>(x_a, x_hp, b_ih_a, b_hh_a, b_out_a, b_sum,
                               b_ih_hp, b_hh_hp, b_out_hp, out);
}